// round 6
// baseline (speedup 1.0000x reference)
#include <cuda_runtime.h>
#include <math.h>

// ---------------------------------------------------------------------------
// Problem constants: B=2, T=2048, C=768, H=12, D=64, Dff=3072, M = B*T = 4096
// ---------------------------------------------------------------------------
#define M_ROWS 4096
#define C_DIM  768
#define QKV_N  2304
#define DFF    3072
#define T_SEQ  2048
#define NHEAD  12
#define HDIM   64

// ---------------------------------------------------------------------------
// Scratch (device globals; allocation-free rule)
// ---------------------------------------------------------------------------
__device__ float g_qkv [M_ROWS * QKV_N];   // 37.7 MB
__device__ float g_attn[M_ROWS * C_DIM];   // 12.6 MB
__device__ float g_tmp [M_ROWS * C_DIM];   // 12.6 MB (proj out, then mlp out)
__device__ float g_out1[M_ROWS * C_DIM];   // 12.6 MB (x + LN(proj))
__device__ float g_h   [M_ROWS * DFF];     // 50.3 MB

// ---------------------------------------------------------------------------
// SGEMM: C = A(MxK) @ B(KxN) + bias[N], optional exact GELU.
// BM=BN=128, BK=8, 256 threads, 8x8 per-thread microtile.
// All of M,N,K are multiples of the tile dims for this problem -> no bounds.
// ---------------------------------------------------------------------------
template<int GELU>
__global__ __launch_bounds__(256)
void sgemm_bias(const float* __restrict__ A, const float* __restrict__ B,
                const float* __restrict__ bias, float* __restrict__ C,
                int M, int N, int K)
{
    __shared__ float As[8][128];
    __shared__ float Bs[8][128];

    const int tid = threadIdx.x;
    const int tx  = tid & 15;        // 0..15 -> col group
    const int ty  = tid >> 4;        // 0..15 -> row group
    const int bx  = blockIdx.x;      // N tile
    const int by  = blockIdx.y;      // M tile

    const int aRow = tid >> 1;             // 0..127
    const int aCol = (tid & 1) << 2;       // 0 or 4
    const int bRow = tid >> 5;             // 0..7
    const int bCol = (tid & 31) << 2;      // 0..124

    const float* Ablk = A + (size_t)(by * 128) * K;
    const float* Bblk = B + bx * 128;

    float acc[8][8];
    #pragma unroll
    for (int i = 0; i < 8; i++)
        #pragma unroll
        for (int j = 0; j < 8; j++) acc[i][j] = 0.f;

    for (int k0 = 0; k0 < K; k0 += 8) {
        float4 av = *(const float4*)(Ablk + (size_t)aRow * K + k0 + aCol);
        As[aCol + 0][aRow] = av.x;
        As[aCol + 1][aRow] = av.y;
        As[aCol + 2][aRow] = av.z;
        As[aCol + 3][aRow] = av.w;
        float4 bv = *(const float4*)(Bblk + (size_t)(k0 + bRow) * N + bCol);
        *(float4*)&Bs[bRow][bCol] = bv;
        __syncthreads();

        #pragma unroll
        for (int kk = 0; kk < 8; kk++) {
            float4 a0 = *(float4*)&As[kk][ty * 8];
            float4 a1 = *(float4*)&As[kk][ty * 8 + 4];
            float4 b0 = *(float4*)&Bs[kk][tx * 8];
            float4 b1 = *(float4*)&Bs[kk][tx * 8 + 4];
            float a[8] = {a0.x, a0.y, a0.z, a0.w, a1.x, a1.y, a1.z, a1.w};
            float b[8] = {b0.x, b0.y, b0.z, b0.w, b1.x, b1.y, b1.z, b1.w};
            #pragma unroll
            for (int i = 0; i < 8; i++)
                #pragma unroll
                for (int j = 0; j < 8; j++)
                    acc[i][j] = fmaf(a[i], b[j], acc[i][j]);
        }
        __syncthreads();
    }

    // epilogue
    #pragma unroll
    for (int i = 0; i < 8; i++) {
        int row = by * 128 + ty * 8 + i;
        #pragma unroll
        for (int j = 0; j < 8; j += 4) {
            int col = bx * 128 + tx * 8 + j;
            float4 bb = *(const float4*)(bias + col);
            float4 v;
            v.x = acc[i][j + 0] + bb.x;
            v.y = acc[i][j + 1] + bb.y;
            v.z = acc[i][j + 2] + bb.z;
            v.w = acc[i][j + 3] + bb.w;
            if (GELU) {
                v.x = 0.5f * v.x * (1.f + erff(v.x * 0.70710678118654752f));
                v.y = 0.5f * v.y * (1.f + erff(v.y * 0.70710678118654752f));
                v.z = 0.5f * v.z * (1.f + erff(v.z * 0.70710678118654752f));
                v.w = 0.5f * v.w * (1.f + erff(v.w * 0.70710678118654752f));
            }
            *(float4*)(C + (size_t)row * N + col) = v;
        }
    }
}

// ---------------------------------------------------------------------------
// Flash attention: block = (q_tile of 64, head, batch). 256 threads (16x16),
// 4x4 per-thread microtile. Q/K/V 64x64 tiles in dyn smem, stride 65.
// P reuses K buffer. Online softmax with shfl reductions over 16-lane groups.
// ---------------------------------------------------------------------------
#define AT_S 65   // shared row stride

__global__ __launch_bounds__(256)
void attn_kernel(const float* __restrict__ qkv, const int* __restrict__ mask,
                 float* __restrict__ out)
{
    extern __shared__ float sh[];
    float* sQ = sh;                 // 64*65
    float* sK = sQ + 64 * AT_S;     // 64*65  (also holds P)
    float* sV = sK + 64 * AT_S;     // 64*65
    __shared__ int sMask[64];

    const int qt = blockIdx.x;      // 0..31
    const int h  = blockIdx.y;      // 0..11
    const int b  = blockIdx.z;      // 0..1
    const int tid = threadIdx.x;
    const int tx = tid & 15;
    const int ty = tid >> 4;

    const int rowBase = b * T_SEQ;
    const int qOff = h * HDIM;
    const int kOff = C_DIM + h * HDIM;
    const int vOff = 2 * C_DIM + h * HDIM;

    // load Q tile (64 rows x 64 cols, float4 per thread x4)
    #pragma unroll
    for (int r = 0; r < 4; r++) {
        int i   = tid + r * 256;         // 0..1023
        int row = i >> 4;
        int c4  = (i & 15) << 2;
        float4 v = *(const float4*)(qkv + (size_t)(rowBase + qt * 64 + row) * QKV_N + qOff + c4);
        float* d = &sQ[row * AT_S + c4];
        d[0] = v.x; d[1] = v.y; d[2] = v.z; d[3] = v.w;
    }

    float m[4], l[4], acc[4][4];
    #pragma unroll
    for (int i = 0; i < 4; i++) {
        m[i] = -1e30f; l[i] = 0.f;
        #pragma unroll
        for (int j = 0; j < 4; j++) acc[i][j] = 0.f;
    }

    for (int kt = 0; kt < T_SEQ / 64; kt++) {
        // load K and V tiles
        #pragma unroll
        for (int r = 0; r < 4; r++) {
            int i   = tid + r * 256;
            int row = i >> 4;
            int c4  = (i & 15) << 2;
            size_t g = (size_t)(rowBase + kt * 64 + row) * QKV_N;
            float4 kv = *(const float4*)(qkv + g + kOff + c4);
            float4 vv = *(const float4*)(qkv + g + vOff + c4);
            float* dk = &sK[row * AT_S + c4];
            dk[0] = kv.x; dk[1] = kv.y; dk[2] = kv.z; dk[3] = kv.w;
            float* dv = &sV[row * AT_S + c4];
            dv[0] = vv.x; dv[1] = vv.y; dv[2] = vv.z; dv[3] = vv.w;
        }
        if (tid < 64) sMask[tid] = mask[rowBase + kt * 64 + tid];
        __syncthreads();

        // S = Q K^T * scale  (rows=queries ty*4+i, cols=keys tx*4+j)
        float s[4][4];
        #pragma unroll
        for (int i = 0; i < 4; i++)
            #pragma unroll
            for (int j = 0; j < 4; j++) s[i][j] = 0.f;

        #pragma unroll 8
        for (int d = 0; d < 64; d++) {
            float a[4], bb[4];
            #pragma unroll
            for (int i = 0; i < 4; i++) a[i]  = sQ[(ty * 4 + i) * AT_S + d];
            #pragma unroll
            for (int j = 0; j < 4; j++) bb[j] = sK[(tx * 4 + j) * AT_S + d];
            #pragma unroll
            for (int i = 0; i < 4; i++)
                #pragma unroll
                for (int j = 0; j < 4; j++)
                    s[i][j] = fmaf(a[i], bb[j], s[i][j]);
        }

        // scale + mask
        const float scale = 0.125f;  // D^-0.5, D=64
        #pragma unroll
        for (int j = 0; j < 4; j++) {
            bool ok = (sMask[tx * 4 + j] != 0);
            #pragma unroll
            for (int i = 0; i < 4; i++)
                s[i][j] = ok ? s[i][j] * scale : -1e30f;
        }

        // per-row max across the 16 lanes owning each row
        float rmax[4];
        #pragma unroll
        for (int i = 0; i < 4; i++) {
            float v = fmaxf(fmaxf(s[i][0], s[i][1]), fmaxf(s[i][2], s[i][3]));
            #pragma unroll
            for (int o = 1; o < 16; o <<= 1)
                v = fmaxf(v, __shfl_xor_sync(0xffffffffu, v, o));
            rmax[i] = v;
        }

        __syncthreads();   // everyone done reading sK -> safe to overwrite with P

        #pragma unroll
        for (int i = 0; i < 4; i++) {
            float mn   = fmaxf(m[i], rmax[i]);
            float corr = __expf(m[i] - mn);
            m[i] = mn;
            float ps = 0.f;
            #pragma unroll
            for (int j = 0; j < 4; j++) {
                float p = __expf(s[i][j] - mn);
                s[i][j] = p;
                ps += p;
            }
            #pragma unroll
            for (int o = 1; o < 16; o <<= 1)
                ps += __shfl_xor_sync(0xffffffffu, ps, o);
            l[i] = l[i] * corr + ps;
            #pragma unroll
            for (int j = 0; j < 4; j++) {
                acc[i][j] *= corr;
                sK[(ty * 4 + i) * AT_S + tx * 4 + j] = s[i][j];  // store P
            }
        }
        __syncthreads();

        // O += P @ V
        #pragma unroll 8
        for (int ss = 0; ss < 64; ss++) {
            float a[4], bb[4];
            #pragma unroll
            for (int i = 0; i < 4; i++) a[i]  = sK[(ty * 4 + i) * AT_S + ss];
            #pragma unroll
            for (int j = 0; j < 4; j++) bb[j] = sV[ss * AT_S + tx * 4 + j];
            #pragma unroll
            for (int i = 0; i < 4; i++)
                #pragma unroll
                for (int j = 0; j < 4; j++)
                    acc[i][j] = fmaf(a[i], bb[j], acc[i][j]);
        }
        __syncthreads();   // before next K/V load
    }

    // write out[b, q, h*64 + d]
    #pragma unroll
    for (int i = 0; i < 4; i++) {
        float inv = 1.f / l[i];
        int row = rowBase + qt * 64 + ty * 4 + i;
        #pragma unroll
        for (int j = 0; j < 4; j++)
            out[(size_t)row * C_DIM + h * HDIM + tx * 4 + j] = acc[i][j] * inv;
    }
}

// ---------------------------------------------------------------------------
// LayerNorm + residual: out[row] = res[row] + LN(y[row]) * gamma + beta
// One block per row, 256 threads, 3 elements/thread (C=768).
// ---------------------------------------------------------------------------
__device__ __forceinline__ float block_sum256(float v)
{
    __shared__ float sh[8];
    int lane = threadIdx.x & 31, w = threadIdx.x >> 5;
    #pragma unroll
    for (int o = 16; o; o >>= 1) v += __shfl_xor_sync(0xffffffffu, v, o);
    if (lane == 0) sh[w] = v;
    __syncthreads();
    if (w == 0) {
        v = (lane < 8) ? sh[lane] : 0.f;
        #pragma unroll
        for (int o = 4; o; o >>= 1) v += __shfl_xor_sync(0xffffffffu, v, o);
        if (lane == 0) sh[0] = v;
    }
    __syncthreads();
    float r = sh[0];
    __syncthreads();   // protect sh reuse on the second call
    return r;
}

__global__ __launch_bounds__(256)
void ln_residual_kernel(const float* __restrict__ y, const float* __restrict__ res,
                        const float* __restrict__ gamma, const float* __restrict__ beta,
                        float* __restrict__ out)
{
    int row = blockIdx.x;
    const float* yr = y   + (size_t)row * C_DIM;
    const float* rr = res + (size_t)row * C_DIM;
    int t = threadIdx.x;

    float v[3];
    #pragma unroll
    for (int i = 0; i < 3; i++) v[i] = yr[t + 256 * i];

    float mean = block_sum256(v[0] + v[1] + v[2]) * (1.f / 768.f);

    float sq = 0.f;
    #pragma unroll
    for (int i = 0; i < 3; i++) { float d = v[i] - mean; sq = fmaf(d, d, sq); }
    float var = block_sum256(sq) * (1.f / 768.f);
    float inv = rsqrtf(var + 1e-5f);

    #pragma unroll
    for (int i = 0; i < 3; i++) {
        int c = t + 256 * i;
        out[(size_t)row * C_DIM + c] = rr[c] + (v[i] - mean) * inv * gamma[c] + beta[c];
    }
}

// ---------------------------------------------------------------------------
// Launch
// ---------------------------------------------------------------------------
extern "C" void kernel_launch(void* const* d_in, const int* in_sizes, int n_in,
                              void* d_out, int out_size)
{
    (void)in_sizes; (void)n_in; (void)out_size;

    const float* x      = (const float*)d_in[0];
    const int*   mask   = (const int*)  d_in[1];
    const float* Wqkv   = (const float*)d_in[2];
    const float* bqkv   = (const float*)d_in[3];
    const float* Wp     = (const float*)d_in[4];
    const float* bp     = (const float*)d_in[5];
    const float* gamma1 = (const float*)d_in[6];
    const float* beta1  = (const float*)d_in[7];
    const float* W1     = (const float*)d_in[8];
    const float* b1     = (const float*)d_in[9];
    const float* W2     = (const float*)d_in[10];
    const float* b2     = (const float*)d_in[11];
    const float* gamma2 = (const float*)d_in[12];
    const float* beta2  = (const float*)d_in[13];
    float* out = (float*)d_out;

    float *qkv, *attn, *tmp, *out1, *hbuf;
    cudaGetSymbolAddress((void**)&qkv,  g_qkv);
    cudaGetSymbolAddress((void**)&attn, g_attn);
    cudaGetSymbolAddress((void**)&tmp,  g_tmp);
    cudaGetSymbolAddress((void**)&out1, g_out1);
    cudaGetSymbolAddress((void**)&hbuf, g_h);

    const int ATTN_SMEM = 3 * 64 * AT_S * (int)sizeof(float);  // 49920 > 48K default
    cudaFuncSetAttribute(attn_kernel, cudaFuncAttributeMaxDynamicSharedMemorySize, ATTN_SMEM);

    // 1) qkv = x @ Wqkv + bqkv
    sgemm_bias<0><<<dim3(QKV_N / 128, M_ROWS / 128), 256>>>(x, Wqkv, bqkv, qkv,
                                                            M_ROWS, QKV_N, C_DIM);
    // 2) flash attention -> (B,T,C)
    attn_kernel<<<dim3(T_SEQ / 64, NHEAD, 2), 256, ATTN_SMEM>>>(qkv, mask, attn);

    // 3) proj = attn @ Wp + bp
    sgemm_bias<0><<<dim3(C_DIM / 128, M_ROWS / 128), 256>>>(attn, Wp, bp, tmp,
                                                            M_ROWS, C_DIM, C_DIM);
    // 4) out1 = x + LN(proj)
    ln_residual_kernel<<<M_ROWS, 256>>>(tmp, x, gamma1, beta1, out1);

    // 5) h = gelu(out1 @ W1 + b1)
    sgemm_bias<1><<<dim3(DFF / 128, M_ROWS / 128), 256>>>(out1, W1, b1, hbuf,
                                                          M_ROWS, DFF, C_DIM);
    // 6) mlp = h @ W2 + b2
    sgemm_bias<0><<<dim3(C_DIM / 128, M_ROWS / 128), 256>>>(hbuf, W2, b2, tmp,
                                                            M_ROWS, C_DIM, DFF);
    // 7) out = out1 + LN(mlp)
    ln_residual_kernel<<<M_ROWS, 256>>>(tmp, out1, gamma2, beta2, out);
}

// round 7
// speedup vs baseline: 1.0016x; 1.0016x over previous
#include <cuda_runtime.h>
#include <math.h>

// ---------------------------------------------------------------------------
// Problem constants: B=2, T=2048, C=768, H=12, D=64, Dff=3072, M = B*T = 4096
// ---------------------------------------------------------------------------
#define M_ROWS 4096
#define C_DIM  768
#define QKV_N  2304
#define DFF    3072
#define T_SEQ  2048
#define NHEAD  12
#define HDIM   64

// ---------------------------------------------------------------------------
// Scratch (device globals; allocation-free rule)
// ---------------------------------------------------------------------------
__device__ float g_qkv [M_ROWS * QKV_N];   // 37.7 MB
__device__ float g_attn[M_ROWS * C_DIM];   // 12.6 MB
__device__ float g_tmp [M_ROWS * C_DIM];   // 12.6 MB (proj out, then mlp out)
__device__ float g_out1[M_ROWS * C_DIM];   // 12.6 MB (x + LN(proj))
__device__ float g_h   [M_ROWS * DFF];     // 50.3 MB

// ---------------------------------------------------------------------------
// SGEMM: C = A(MxK) @ B(KxN) + bias[N], optional exact GELU.
// BM=BN=128, BK=8, 256 threads, 8x8 per-thread microtile.
// All of M,N,K are multiples of the tile dims for this problem -> no bounds.
// ---------------------------------------------------------------------------
template<int GELU>
__global__ __launch_bounds__(256)
void sgemm_bias(const float* __restrict__ A, const float* __restrict__ B,
                const float* __restrict__ bias, float* __restrict__ C,
                int M, int N, int K)
{
    __shared__ float As[8][128];
    __shared__ float Bs[8][128];

    const int tid = threadIdx.x;
    const int tx  = tid & 15;        // 0..15 -> col group
    const int ty  = tid >> 4;        // 0..15 -> row group
    const int bx  = blockIdx.x;      // N tile
    const int by  = blockIdx.y;      // M tile

    const int aRow = tid >> 1;             // 0..127
    const int aCol = (tid & 1) << 2;       // 0 or 4
    const int bRow = tid >> 5;             // 0..7
    const int bCol = (tid & 31) << 2;      // 0..124

    const float* Ablk = A + (size_t)(by * 128) * K;
    const float* Bblk = B + bx * 128;

    float acc[8][8];
    #pragma unroll
    for (int i = 0; i < 8; i++)
        #pragma unroll
        for (int j = 0; j < 8; j++) acc[i][j] = 0.f;

    for (int k0 = 0; k0 < K; k0 += 8) {
        float4 av = *(const float4*)(Ablk + (size_t)aRow * K + k0 + aCol);
        As[aCol + 0][aRow] = av.x;
        As[aCol + 1][aRow] = av.y;
        As[aCol + 2][aRow] = av.z;
        As[aCol + 3][aRow] = av.w;
        float4 bv = *(const float4*)(Bblk + (size_t)(k0 + bRow) * N + bCol);
        *(float4*)&Bs[bRow][bCol] = bv;
        __syncthreads();

        #pragma unroll
        for (int kk = 0; kk < 8; kk++) {
            float4 a0 = *(float4*)&As[kk][ty * 8];
            float4 a1 = *(float4*)&As[kk][ty * 8 + 4];
            float4 b0 = *(float4*)&Bs[kk][tx * 8];
            float4 b1 = *(float4*)&Bs[kk][tx * 8 + 4];
            float a[8] = {a0.x, a0.y, a0.z, a0.w, a1.x, a1.y, a1.z, a1.w};
            float b[8] = {b0.x, b0.y, b0.z, b0.w, b1.x, b1.y, b1.z, b1.w};
            #pragma unroll
            for (int i = 0; i < 8; i++)
                #pragma unroll
                for (int j = 0; j < 8; j++)
                    acc[i][j] = fmaf(a[i], b[j], acc[i][j]);
        }
        __syncthreads();
    }

    // epilogue
    #pragma unroll
    for (int i = 0; i < 8; i++) {
        int row = by * 128 + ty * 8 + i;
        #pragma unroll
        for (int j = 0; j < 8; j += 4) {
            int col = bx * 128 + tx * 8 + j;
            float4 bb = *(const float4*)(bias + col);
            float4 v;
            v.x = acc[i][j + 0] + bb.x;
            v.y = acc[i][j + 1] + bb.y;
            v.z = acc[i][j + 2] + bb.z;
            v.w = acc[i][j + 3] + bb.w;
            if (GELU) {
                v.x = 0.5f * v.x * (1.f + erff(v.x * 0.70710678118654752f));
                v.y = 0.5f * v.y * (1.f + erff(v.y * 0.70710678118654752f));
                v.z = 0.5f * v.z * (1.f + erff(v.z * 0.70710678118654752f));
                v.w = 0.5f * v.w * (1.f + erff(v.w * 0.70710678118654752f));
            }
            *(float4*)(C + (size_t)row * N + col) = v;
        }
    }
}

// ---------------------------------------------------------------------------
// Flash attention: block = (q_tile of 64, head, batch). 256 threads (16x16),
// 4x4 per-thread microtile. Q/K/V 64x64 tiles in dyn smem, stride 65.
// P reuses K buffer. Online softmax with shfl reductions over 16-lane groups.
// ---------------------------------------------------------------------------
#define AT_S 65   // shared row stride

__global__ __launch_bounds__(256)
void attn_kernel(const float* __restrict__ qkv, const int* __restrict__ mask,
                 float* __restrict__ out)
{
    extern __shared__ float sh[];
    float* sQ = sh;                 // 64*65
    float* sK = sQ + 64 * AT_S;     // 64*65  (also holds P)
    float* sV = sK + 64 * AT_S;     // 64*65
    __shared__ int sMask[64];

    const int qt = blockIdx.x;      // 0..31
    const int h  = blockIdx.y;      // 0..11
    const int b  = blockIdx.z;      // 0..1
    const int tid = threadIdx.x;
    const int tx = tid & 15;
    const int ty = tid >> 4;

    const int rowBase = b * T_SEQ;
    const int qOff = h * HDIM;
    const int kOff = C_DIM + h * HDIM;
    const int vOff = 2 * C_DIM + h * HDIM;

    // load Q tile (64 rows x 64 cols, float4 per thread x4)
    #pragma unroll
    for (int r = 0; r < 4; r++) {
        int i   = tid + r * 256;         // 0..1023
        int row = i >> 4;
        int c4  = (i & 15) << 2;
        float4 v = *(const float4*)(qkv + (size_t)(rowBase + qt * 64 + row) * QKV_N + qOff + c4);
        float* d = &sQ[row * AT_S + c4];
        d[0] = v.x; d[1] = v.y; d[2] = v.z; d[3] = v.w;
    }

    float m[4], l[4], acc[4][4];
    #pragma unroll
    for (int i = 0; i < 4; i++) {
        m[i] = -1e30f; l[i] = 0.f;
        #pragma unroll
        for (int j = 0; j < 4; j++) acc[i][j] = 0.f;
    }

    for (int kt = 0; kt < T_SEQ / 64; kt++) {
        // load K and V tiles
        #pragma unroll
        for (int r = 0; r < 4; r++) {
            int i   = tid + r * 256;
            int row = i >> 4;
            int c4  = (i & 15) << 2;
            size_t g = (size_t)(rowBase + kt * 64 + row) * QKV_N;
            float4 kv = *(const float4*)(qkv + g + kOff + c4);
            float4 vv = *(const float4*)(qkv + g + vOff + c4);
            float* dk = &sK[row * AT_S + c4];
            dk[0] = kv.x; dk[1] = kv.y; dk[2] = kv.z; dk[3] = kv.w;
            float* dv = &sV[row * AT_S + c4];
            dv[0] = vv.x; dv[1] = vv.y; dv[2] = vv.z; dv[3] = vv.w;
        }
        if (tid < 64) sMask[tid] = mask[rowBase + kt * 64 + tid];
        __syncthreads();

        // S = Q K^T * scale  (rows=queries ty*4+i, cols=keys tx*4+j)
        float s[4][4];
        #pragma unroll
        for (int i = 0; i < 4; i++)
            #pragma unroll
            for (int j = 0; j < 4; j++) s[i][j] = 0.f;

        #pragma unroll 8
        for (int d = 0; d < 64; d++) {
            float a[4], bb[4];
            #pragma unroll
            for (int i = 0; i < 4; i++) a[i]  = sQ[(ty * 4 + i) * AT_S + d];
            #pragma unroll
            for (int j = 0; j < 4; j++) bb[j] = sK[(tx * 4 + j) * AT_S + d];
            #pragma unroll
            for (int i = 0; i < 4; i++)
                #pragma unroll
                for (int j = 0; j < 4; j++)
                    s[i][j] = fmaf(a[i], bb[j], s[i][j]);
        }

        // scale + mask
        const float scale = 0.125f;  // D^-0.5, D=64
        #pragma unroll
        for (int j = 0; j < 4; j++) {
            bool ok = (sMask[tx * 4 + j] != 0);
            #pragma unroll
            for (int i = 0; i < 4; i++)
                s[i][j] = ok ? s[i][j] * scale : -1e30f;
        }

        // per-row max across the 16 lanes owning each row
        float rmax[4];
        #pragma unroll
        for (int i = 0; i < 4; i++) {
            float v = fmaxf(fmaxf(s[i][0], s[i][1]), fmaxf(s[i][2], s[i][3]));
            #pragma unroll
            for (int o = 1; o < 16; o <<= 1)
                v = fmaxf(v, __shfl_xor_sync(0xffffffffu, v, o));
            rmax[i] = v;
        }

        __syncthreads();   // everyone done reading sK -> safe to overwrite with P

        #pragma unroll
        for (int i = 0; i < 4; i++) {
            float mn   = fmaxf(m[i], rmax[i]);
            float corr = __expf(m[i] - mn);
            m[i] = mn;
            float ps = 0.f;
            #pragma unroll
            for (int j = 0; j < 4; j++) {
                float p = __expf(s[i][j] - mn);
                s[i][j] = p;
                ps += p;
            }
            #pragma unroll
            for (int o = 1; o < 16; o <<= 1)
                ps += __shfl_xor_sync(0xffffffffu, ps, o);
            l[i] = l[i] * corr + ps;
            #pragma unroll
            for (int j = 0; j < 4; j++) {
                acc[i][j] *= corr;
                sK[(ty * 4 + i) * AT_S + tx * 4 + j] = s[i][j];  // store P
            }
        }
        __syncthreads();

        // O += P @ V
        #pragma unroll 8
        for (int ss = 0; ss < 64; ss++) {
            float a[4], bb[4];
            #pragma unroll
            for (int i = 0; i < 4; i++) a[i]  = sK[(ty * 4 + i) * AT_S + ss];
            #pragma unroll
            for (int j = 0; j < 4; j++) bb[j] = sV[ss * AT_S + tx * 4 + j];
            #pragma unroll
            for (int i = 0; i < 4; i++)
                #pragma unroll
                for (int j = 0; j < 4; j++)
                    acc[i][j] = fmaf(a[i], bb[j], acc[i][j]);
        }
        __syncthreads();   // before next K/V load
    }

    // write out[b, q, h*64 + d]
    #pragma unroll
    for (int i = 0; i < 4; i++) {
        float inv = 1.f / l[i];
        int row = rowBase + qt * 64 + ty * 4 + i;
        #pragma unroll
        for (int j = 0; j < 4; j++)
            out[(size_t)row * C_DIM + h * HDIM + tx * 4 + j] = acc[i][j] * inv;
    }
}

// ---------------------------------------------------------------------------
// LayerNorm + residual: out[row] = res[row] + LN(y[row]) * gamma + beta
// One block per row, 256 threads, 3 elements/thread (C=768).
// ---------------------------------------------------------------------------
__device__ __forceinline__ float block_sum256(float v)
{
    __shared__ float sh[8];
    int lane = threadIdx.x & 31, w = threadIdx.x >> 5;
    #pragma unroll
    for (int o = 16; o; o >>= 1) v += __shfl_xor_sync(0xffffffffu, v, o);
    if (lane == 0) sh[w] = v;
    __syncthreads();
    if (w == 0) {
        v = (lane < 8) ? sh[lane] : 0.f;
        #pragma unroll
        for (int o = 4; o; o >>= 1) v += __shfl_xor_sync(0xffffffffu, v, o);
        if (lane == 0) sh[0] = v;
    }
    __syncthreads();
    float r = sh[0];
    __syncthreads();   // protect sh reuse on the second call
    return r;
}

__global__ __launch_bounds__(256)
void ln_residual_kernel(const float* __restrict__ y, const float* __restrict__ res,
                        const float* __restrict__ gamma, const float* __restrict__ beta,
                        float* __restrict__ out)
{
    int row = blockIdx.x;
    const float* yr = y   + (size_t)row * C_DIM;
    const float* rr = res + (size_t)row * C_DIM;
    int t = threadIdx.x;

    float v[3];
    #pragma unroll
    for (int i = 0; i < 3; i++) v[i] = yr[t + 256 * i];

    float mean = block_sum256(v[0] + v[1] + v[2]) * (1.f / 768.f);

    float sq = 0.f;
    #pragma unroll
    for (int i = 0; i < 3; i++) { float d = v[i] - mean; sq = fmaf(d, d, sq); }
    float var = block_sum256(sq) * (1.f / 768.f);
    float inv = rsqrtf(var + 1e-5f);

    #pragma unroll
    for (int i = 0; i < 3; i++) {
        int c = t + 256 * i;
        out[(size_t)row * C_DIM + c] = rr[c] + (v[i] - mean) * inv * gamma[c] + beta[c];
    }
}

// ---------------------------------------------------------------------------
// Launch
// ---------------------------------------------------------------------------
extern "C" void kernel_launch(void* const* d_in, const int* in_sizes, int n_in,
                              void* d_out, int out_size)
{
    (void)in_sizes; (void)n_in; (void)out_size;

    const float* x      = (const float*)d_in[0];
    const int*   mask   = (const int*)  d_in[1];
    const float* Wqkv   = (const float*)d_in[2];
    const float* bqkv   = (const float*)d_in[3];
    const float* Wp     = (const float*)d_in[4];
    const float* bp     = (const float*)d_in[5];
    const float* gamma1 = (const float*)d_in[6];
    const float* beta1  = (const float*)d_in[7];
    const float* W1     = (const float*)d_in[8];
    const float* b1     = (const float*)d_in[9];
    const float* W2     = (const float*)d_in[10];
    const float* b2     = (const float*)d_in[11];
    const float* gamma2 = (const float*)d_in[12];
    const float* beta2  = (const float*)d_in[13];
    float* out = (float*)d_out;

    float *qkv, *attn, *tmp, *out1, *hbuf;
    cudaGetSymbolAddress((void**)&qkv,  g_qkv);
    cudaGetSymbolAddress((void**)&attn, g_attn);
    cudaGetSymbolAddress((void**)&tmp,  g_tmp);
    cudaGetSymbolAddress((void**)&out1, g_out1);
    cudaGetSymbolAddress((void**)&hbuf, g_h);

    const int ATTN_SMEM = 3 * 64 * AT_S * (int)sizeof(float);  // 49920 > 48K default
    cudaFuncSetAttribute(attn_kernel, cudaFuncAttributeMaxDynamicSharedMemorySize, ATTN_SMEM);

    // 1) qkv = x @ Wqkv + bqkv
    sgemm_bias<0><<<dim3(QKV_N / 128, M_ROWS / 128), 256>>>(x, Wqkv, bqkv, qkv,
                                                            M_ROWS, QKV_N, C_DIM);
    // 2) flash attention -> (B,T,C)
    attn_kernel<<<dim3(T_SEQ / 64, NHEAD, 2), 256, ATTN_SMEM>>>(qkv, mask, attn);

    // 3) proj = attn @ Wp + bp
    sgemm_bias<0><<<dim3(C_DIM / 128, M_ROWS / 128), 256>>>(attn, Wp, bp, tmp,
                                                            M_ROWS, C_DIM, C_DIM);
    // 4) out1 = x + LN(proj)
    ln_residual_kernel<<<M_ROWS, 256>>>(tmp, x, gamma1, beta1, out1);

    // 5) h = gelu(out1 @ W1 + b1)
    sgemm_bias<1><<<dim3(DFF / 128, M_ROWS / 128), 256>>>(out1, W1, b1, hbuf,
                                                          M_ROWS, DFF, C_DIM);
    // 6) mlp = h @ W2 + b2
    sgemm_bias<0><<<dim3(C_DIM / 128, M_ROWS / 128), 256>>>(hbuf, W2, b2, tmp,
                                                            M_ROWS, C_DIM, DFF);
    // 7) out = out1 + LN(mlp)
    ln_residual_kernel<<<M_ROWS, 256>>>(tmp, out1, gamma2, beta2, out);
}